// round 7
// baseline (speedup 1.0000x reference)
#include <cuda_runtime.h>

// RvNN fused kernel v5: v4 k-pair packed f32x2 math, restructured to
// 256-thread blocks with ~101KB smem so 2 blocks co-reside per SM
// (decorrelated barriers cover latency). Double-buffered 8KB weight tiles.

#define DEVINL __device__ __forceinline__
typedef unsigned long long u64;

constexpr int NTH = 256;
constexpr int BB  = 8;
// stage1 rows M1 = 4*BB = 32, stage2 rows M2 = 2*BB = 16

// packed weight segments (float2 units) in g_packed
constexpr int OP_WC2 = 0;       // 64 kp x 256
constexpr int OP_WP2 = 16384;   // 64 kp x 256
constexpr int OP_WL1 = 32768;   // 256 kp x 128
constexpr int NPACK  = 65536;   // 512 KB

__device__ __align__(16) float2 g_packed[NPACK];

// ---- shared memory layout (float offsets) ----
constexpr int SM_U    = 0;        // U / V / H: 32*128 = 4096
constexpr int SM_CHPA = 4096;     // [32][512] = 16384 (X staging aliases)
constexpr int SM_WT   = 20480;    // 4096 floats = 2 bufs x 1024 u64 (16KB)
constexpr int SM_Y    = 24576;    // 384
constexpr int SM_S12  = 24960;    // 384
constexpr int SM_TOT  = 25344;    // 101376 bytes

DEVINL float sanf(float x) {
    if (isnan(x)) return 0.0f;
    if (isinf(x)) return 9999.0f;
    return x;
}

DEVINL float fast_tanh(float x) {
    float ax = fabsf(x) * 2.8853900817779268f;  // 2*log2(e)
    float e; asm("ex2.approx.f32 %0, %1;" : "=f"(e) : "f"(ax));
    float r; asm("rcp.approx.f32 %0, %1;" : "=f"(r) : "f"(e + 1.0f));
    float t = fmaf(-2.0f, r, 1.0f);
    return copysignf(t, x);
}

DEVINL void fma2(u64& acc, u64 a, u64 b) {
    asm("fma.rn.f32x2 %0, %1, %2, %0;" : "+l"(acc) : "l"(a), "l"(b));
}
DEVINL float2 unpk(u64 v) {
    float2 r; asm("mov.b64 {%0, %1}, %2;" : "=f"(r.x), "=f"(r.y) : "l"(v)); return r;
}

DEVINL void cpa16(void* dst, const void* src) {
    unsigned sa = (unsigned)__cvta_generic_to_shared(dst);
    asm volatile("cp.async.cg.shared.global [%0], [%1], 16;" :: "r"(sa), "l"(src));
}
DEVINL void cpa_commit() { asm volatile("cp.async.commit_group;"); }
DEVINL void cpa_wait0()  { asm volatile("cp.async.wait_group 0;"); }

// ---------- prepack: W[K][N] -> g_packed[kp][c] = (W[2kp][c], W[2kp+1][c]) ----------
__global__ void prepack_kernel(const float* __restrict__ Wc2,
                               const float* __restrict__ Wp2,
                               const float* __restrict__ Wl1)
{
    int idx = blockIdx.x * blockDim.x + threadIdx.x;
    if (idx >= NPACK) return;
    const float* W; int loc, N;
    if (idx < OP_WP2)      { W = Wc2; loc = idx;           N = 256; }
    else if (idx < OP_WL1) { W = Wp2; loc = idx - OP_WP2;  N = 256; }
    else                   { W = Wl1; loc = idx - OP_WL1;  N = 128; }
    int kp = (N == 256) ? (loc >> 8) : (loc >> 7);
    int c  = loc & (N - 1);
    g_packed[idx] = make_float2(W[(2 * kp) * N + c], W[(2 * kp + 1) * N + c]);
}

// ---------- layer1: A[M][KA] @ W[KA][128] + b -> prelu -> U row-major ----------
// 8 warps: ty in [0,8), cols c = tx + 32j.
template<int M, int KA>
DEVINL void layer1(const float* __restrict__ A, const float* __restrict__ WT,
                   const float* __restrict__ bg, float alpha,
                   float* __restrict__ U, int tx, int ty)
{
    constexpr int RPT = M / 8;
    float acc[RPT][4];
#pragma unroll
    for (int r = 0; r < RPT; r++)
#pragma unroll
        for (int j = 0; j < 4; j++) acc[r][j] = 0.0f;

#pragma unroll
    for (int k = 0; k < KA; k += 4) {
        float a[RPT][4];
#pragma unroll
        for (int r = 0; r < RPT; r++) {
            float4 v = *(const float4*)&A[(ty * RPT + r) * KA + k];
            a[r][0] = v.x; a[r][1] = v.y; a[r][2] = v.z; a[r][3] = v.w;
        }
#pragma unroll
        for (int j4 = 0; j4 < 4; j4++) {
            float w[4];
#pragma unroll
            for (int j = 0; j < 4; j++) w[j] = WT[(k + j4) * 128 + tx + 32 * j];
#pragma unroll
            for (int r = 0; r < RPT; r++)
#pragma unroll
                for (int j = 0; j < 4; j++)
                    acc[r][j] = fmaf(a[r][j4], w[j], acc[r][j]);
        }
    }
#pragma unroll
    for (int r = 0; r < RPT; r++)
#pragma unroll
        for (int j = 0; j < 4; j++) {
            int c = tx + 32 * j;
            float v = acc[r][j] + bg[c];
            v = (v >= 0.0f) ? v : alpha * v;
            U[(ty * RPT + r) * 128 + c] = v;
        }
}

// ---------- layer2: U[M][128] @ W[128][256] + b -> tanh -> CHPA[:, colOff..+256) ----------
// k-pair packed. cidx in [0,128): col-pairs cidx, cidx+128. 2 row-groups.
// 16 tiles of 4kp x 256 u64 (8KB), double buffered.
template<int M>
DEVINL void layer2(const float* __restrict__ U, const float2* __restrict__ Pg,
                   const float* __restrict__ bg, float* __restrict__ CH, int colOff,
                   u64* __restrict__ WT, int tid)
{
    constexpr int RPT = M / 2;
    const int cidx = tid & 127;
    const int r0 = (tid >> 7) * RPT;
    const float bias0 = bg[cidx], bias1 = bg[cidx + 128];

    u64 acc[RPT][2];
#pragma unroll
    for (int r = 0; r < RPT; r++) { acc[r][0] = 0ull; acc[r][1] = 0ull; }

    // preload tile 0 (4 kp x 256 = 1024 u64 = 8KB -> 512 x 16B)
    for (int s = tid; s < 512; s += NTH)
        cpa16(WT + s * 2, Pg + s * 2);
    cpa_commit(); cpa_wait0();
    __syncthreads();

    for (int t = 0; t < 16; t++) {
        const u64* wt = WT + (t & 1) * 1024;
        if (t + 1 < 16) {
            u64* nb = WT + ((t + 1) & 1) * 1024;
            const float2* ns = Pg + (t + 1) * 1024;
            for (int s = tid; s < 512; s += NTH)
                cpa16(nb + s * 2, ns + s * 2);
            cpa_commit();
        }
#pragma unroll
        for (int kpp = 0; kpp < 4; kpp += 2) {
            u64 w00 = wt[kpp * 256 + cidx];
            u64 w01 = wt[kpp * 256 + cidx + 128];
            u64 w10 = wt[(kpp + 1) * 256 + cidx];
            u64 w11 = wt[(kpp + 1) * 256 + cidx + 128];
            const int kf = 2 * (t * 4 + kpp);  // float offset, 16B aligned
#pragma unroll
            for (int r = 0; r < RPT; r++) {
                ulonglong2 a = *(const ulonglong2*)&U[(r0 + r) * 128 + kf];
                fma2(acc[r][0], a.x, w00);
                fma2(acc[r][1], a.x, w01);
                fma2(acc[r][0], a.y, w10);
                fma2(acc[r][1], a.y, w11);
            }
        }
        cpa_wait0();
        __syncthreads();
    }
#pragma unroll
    for (int r = 0; r < RPT; r++) {
        float2 v0 = unpk(acc[r][0]);
        float2 v1 = unpk(acc[r][1]);
        CH[(r0 + r) * 512 + colOff + cidx]       = fast_tanh(v0.x + v0.y + bias0);
        CH[(r0 + r) * 512 + colOff + cidx + 128] = fast_tanh(v1.x + v1.y + bias1);
    }
}

// ---------- layer3: CHPA[M][512] @ Wl1[512][128] + b -> tanh -> H[M][128] ----------
// cidx in [0,64): col-pairs cidx, cidx+64. 4 row-groups.
// 32 tiles of 8kp x 128 u64 (8KB), double buffered.
template<int M>
DEVINL void layer3(const float* __restrict__ CP, const float2* __restrict__ Pg,
                   const float* __restrict__ bl1, float* __restrict__ H,
                   u64* __restrict__ WT, int tid)
{
    constexpr int RPT = M / 4;
    const int cidx = tid & 63;
    const int r0 = (tid >> 6) * RPT;
    const float bias0 = bl1[cidx], bias1 = bl1[cidx + 64];

    u64 acc[RPT][2];
#pragma unroll
    for (int r = 0; r < RPT; r++) { acc[r][0] = 0ull; acc[r][1] = 0ull; }

    for (int s = tid; s < 512; s += NTH)
        cpa16(WT + s * 2, Pg + s * 2);
    cpa_commit(); cpa_wait0();
    __syncthreads();

    for (int t = 0; t < 32; t++) {
        const u64* wt = WT + (t & 1) * 1024;
        if (t + 1 < 32) {
            u64* nb = WT + ((t + 1) & 1) * 1024;
            const float2* ns = Pg + (t + 1) * 1024;
            for (int s = tid; s < 512; s += NTH)
                cpa16(nb + s * 2, ns + s * 2);
            cpa_commit();
        }
#pragma unroll
        for (int kpp = 0; kpp < 8; kpp += 2) {
            u64 w00 = wt[kpp * 128 + cidx];
            u64 w01 = wt[kpp * 128 + cidx + 64];
            u64 w10 = wt[(kpp + 1) * 128 + cidx];
            u64 w11 = wt[(kpp + 1) * 128 + cidx + 64];
            const int kf = 2 * (t * 8 + kpp);
#pragma unroll
            for (int r = 0; r < RPT; r++) {
                ulonglong2 a = *(const ulonglong2*)&CP[(r0 + r) * 512 + kf];
                fma2(acc[r][0], a.x, w00);
                fma2(acc[r][1], a.x, w01);
                fma2(acc[r][0], a.y, w10);
                fma2(acc[r][1], a.y, w11);
            }
        }
        cpa_wait0();
        __syncthreads();
    }
#pragma unroll
    for (int r = 0; r < RPT; r++) {
        float2 v0 = unpk(acc[r][0]);
        float2 v1 = unpk(acc[r][1]);
        H[(r0 + r) * 128 + cidx]      = fast_tanh(v0.x + v0.y + bias0);
        H[(r0 + r) * 128 + cidx + 64] = fast_tanh(v1.x + v1.y + bias1);
    }
}

// ---------- layer4: H[M][128] @ Wl2[128][32] + b -> prelu -> S12 / out ----------
template<int M, bool FINAL>
DEVINL void layer4(const float* __restrict__ H, const float* __restrict__ WT,
                   const float* __restrict__ bl2, float al,
                   float* __restrict__ S12, float* __restrict__ out,
                   int b0, int nb, int tx, int ty)
{
    constexpr int RPT = M / 8;
    float acc[RPT];
#pragma unroll
    for (int r = 0; r < RPT; r++) acc[r] = 0.0f;
#pragma unroll
    for (int k = 0; k < 128; k += 4) {
        float a[RPT][4];
#pragma unroll
        for (int r = 0; r < RPT; r++) {
            float4 v = *(const float4*)&H[(ty * RPT + r) * 128 + k];
            a[r][0] = v.x; a[r][1] = v.y; a[r][2] = v.z; a[r][3] = v.w;
        }
#pragma unroll
        for (int j = 0; j < 4; j++) {
            float wv = WT[(k + j) * 32 + tx];
#pragma unroll
            for (int r = 0; r < RPT; r++) acc[r] = fmaf(a[r][j], wv, acc[r]);
        }
    }
#pragma unroll
    for (int r = 0; r < RPT; r++) {
        float v = acc[r] + bl2[tx];
        v = (v >= 0.0f) ? v : al * v;
        int row = ty * RPT + r;
        if (FINAL) {
            int be = b0 + (row >> 1);
            if (be < nb) out[(size_t)be * 64 + (row & 1) * 32 + tx] = v;
        } else {
            if (tx < 12) S12[row * 12 + tx] = v;
        }
    }
}

// ---------- full combine() pipeline for M rows ----------
template<int M, bool FINAL>
DEVINL void pipeline(float* sm, int tid,
                     const float* Wc1, const float* bc1, float ac,
                     const float* bc2,
                     const float* Wp1, const float* bp1, float ap,
                     const float* bp2,
                     const float* bl1,
                     const float* Wl2, const float* bl2, float al,
                     float* out, int b0, int nb)
{
    float* U    = sm + SM_U;      // also H (alias)
    float* CHPA = sm + SM_CHPA;
    u64*   WT2  = (u64*)(sm + SM_WT);
    float* WT   = sm + SM_WT;
    float* X    = sm + SM_CHPA;   // alias (consumed before CHPA written)
    float* Y    = sm + SM_Y;
    float* S12  = sm + SM_S12;
    const int tx = tid & 31, ty = tid >> 5;

    // A1: U = prelu(X @ Wc1 + bc1)
    for (int i = tid; i < 24 * 128; i += NTH) WT[i] = Wc1[i];
    __syncthreads();
    layer1<M, 24>(X, WT, bc1, ac, U, tx, ty);
    __syncthreads();
    // B1: ch -> CHPA cols [0,256)
    layer2<M>(U, g_packed + OP_WC2, bc2, CHPA, 0, WT2, tid);
    __syncthreads();
    // A2: V = prelu(Y @ Wp1 + bp1) (overwrites U)
    for (int i = tid; i < 12 * 128; i += NTH) WT[i] = Wp1[i];
    __syncthreads();
    layer1<M, 12>(Y, WT, bp1, ap, U, tx, ty);
    __syncthreads();
    // B2: pa -> CHPA cols [256,512)
    layer2<M>(U, g_packed + OP_WP2, bp2, CHPA, 256, WT2, tid);
    __syncthreads();
    // C: h = tanh(CHPA @ Wl1 + bl1) -> H (aliases U)
    layer3<M>(CHPA, g_packed + OP_WL1, bl1, U, WT2, tid);
    __syncthreads();
    // D: out = prelu(h @ Wl2 + bl2)
    for (int i = tid; i < 128 * 32; i += NTH) WT[i] = Wl2[i];
    __syncthreads();
    layer4<M, FINAL>(U, WT, bl2, al, S12, out, b0, nb, tx, ty);
}

__global__ void __launch_bounds__(NTH, 2)
rvnn_kernel(const float* __restrict__ level1, const float* __restrict__ level2,
            const float* __restrict__ level3,
            const float* __restrict__ Wc1, const float* __restrict__ bc1, const float* __restrict__ ac,
            const float* __restrict__ bc2,
            const float* __restrict__ Wp1, const float* __restrict__ bp1, const float* __restrict__ ap,
            const float* __restrict__ bp2,
            const float* __restrict__ bl1,
            const float* __restrict__ Wl2, const float* __restrict__ bl2, const float* __restrict__ al,
            float* __restrict__ out, int nb)
{
    extern __shared__ float sm[];
    const int tid = threadIdx.x;
    const int b0 = blockIdx.x * BB;
    const float acv = *ac, apv = *ap, alv = *al;

    float* X   = sm + SM_CHPA;
    float* Y   = sm + SM_Y;
    float* S12 = sm + SM_S12;

    // ---- stage 1 input staging (rows = BB*4 = 32) ----
    {
        const float* src = level3 + (size_t)b0 * 96;
        int lim = (nb - b0 < BB ? nb - b0 : BB) * 96;
        for (int i = tid; i < BB * 96; i += NTH) {
            float v = (i < lim) ? sanf(src[i]) : 0.0f;
            int be = i / 96, rem = i % 96, c = rem / 12, k = rem % 12;
            int p = c >> 1, s = c & 1;
            X[(be * 4 + p) * 24 + (1 - s) * 12 + k] = v;
        }
    }
    {
        const float* src = level2 + (size_t)b0 * 48;
        int lim = (nb - b0 < BB ? nb - b0 : BB) * 48;
        for (int i = tid; i < BB * 48; i += NTH) {
            float v = (i < lim) ? sanf(src[i]) : 0.0f;
            int be = i / 48, rem = i % 48, p = rem / 12, k = rem % 12;
            Y[(be * 4 + p) * 12 + k] = v;
        }
    }
    __syncthreads();

    pipeline<32, false>(sm, tid, Wc1, bc1, acv, bc2, Wp1, bp1, apv,
                        bp2, bl1, Wl2, bl2, alv, out, b0, nb);
    __syncthreads();

    // ---- stage 2 input staging (rows = BB*2 = 16) ----
    for (int i = tid; i < 16 * 24; i += NTH) {
        int r2 = i / 24, k24 = i % 24, be = r2 >> 1, p = r2 & 1;
        int j = 2 * p + (k24 < 12 ? 1 : 0);
        int k = (k24 < 12) ? k24 : (k24 - 12);
        X[r2 * 24 + k24] = sanf(S12[(be * 4 + j) * 12 + k]);
    }
    {
        const float* src = level1 + (size_t)b0 * 24;
        int lim = (nb - b0 < BB ? nb - b0 : BB) * 24;
        for (int i = tid; i < BB * 24; i += NTH) {
            float v = (i < lim) ? sanf(src[i]) : 0.0f;
            int be = i / 24, rem = i % 24, p = rem / 12, k = rem % 12;
            Y[(be * 2 + p) * 12 + k] = v;
        }
    }
    __syncthreads();

    pipeline<16, true>(sm, tid, Wc1, bc1, acv, bc2, Wp1, bp1, apv,
                       bp2, bl1, Wl2, bl2, alv, out, b0, nb);
}

extern "C" void kernel_launch(void* const* d_in, const int* in_sizes, int n_in,
                              void* d_out, int out_size) {
    const float* level1 = (const float*)d_in[0];
    const float* level2 = (const float*)d_in[1];
    const float* level3 = (const float*)d_in[2];
    const float* Wc1 = (const float*)d_in[3];
    const float* bc1 = (const float*)d_in[4];
    const float* ac  = (const float*)d_in[5];
    const float* Wc2 = (const float*)d_in[6];
    const float* bc2 = (const float*)d_in[7];
    const float* Wp1 = (const float*)d_in[8];
    const float* bp1 = (const float*)d_in[9];
    const float* ap  = (const float*)d_in[10];
    const float* Wp2 = (const float*)d_in[11];
    const float* bp2 = (const float*)d_in[12];
    const float* Wl1 = (const float*)d_in[13];
    const float* bl1 = (const float*)d_in[14];
    const float* Wl2 = (const float*)d_in[15];
    const float* bl2 = (const float*)d_in[16];
    const float* al  = (const float*)d_in[17];
    float* out = (float*)d_out;

    int nb = in_sizes[0] / 24;
    int grid = (nb + BB - 1) / BB;
    size_t smem = (size_t)SM_TOT * sizeof(float);  // 101376 B

    prepack_kernel<<<(NPACK + 255) / 256, 256>>>(Wc2, Wp2, Wl1);

    cudaFuncSetAttribute(rvnn_kernel, cudaFuncAttributeMaxDynamicSharedMemorySize, (int)smem);
    rvnn_kernel<<<grid, NTH, smem>>>(level1, level2, level3, Wc1, bc1, ac, bc2,
                                     Wp1, bp1, ap, bp2, bl1, Wl2, bl2, al,
                                     out, nb);
}

// round 8
// speedup vs baseline: 2.0964x; 2.0964x over previous
#include <cuda_runtime.h>

// RvNN fused kernel v6: layer2/layer3 on tf32 mma.sync.m16n8k8 tensor cores,
// fragment-order prepacked weights, padded smem strides, split-K layer3.

#define DEVINL __device__ __forceinline__
typedef unsigned int u32;
typedef unsigned long long u64;

constexpr int NTH = 512;
constexpr int BB  = 16;

// prepacked B-fragment segments (float2 units): [ks][ntile][lane] = (b0,b1)
constexpr int OC2 = 0;       // Wc2: 16 ks x 32 nt x 32
constexpr int OP2 = 16384;   // Wp2
constexpr int OL1 = 32768;   // Wl1: 64 ks x 16 nt x 32
constexpr int NPAIR = 65536; // 512 KB
__device__ __align__(16) float2 g_packed[NPAIR];

// ---- smem layout (float offsets) ----
constexpr int STRU = 132;    // U/H row stride (conflict-free frag loads)
constexpr int STRC = 516;    // CHPA row stride
constexpr int SM_U    = 0;                 // 64*132 = 8448
constexpr int SM_CHPA = 8448;              // 64*516 = 33024 (X staging aliases)
constexpr int SM_WT   = 41472;             // 8448 (tiles: 2 x 2048 pairs; PART: 64x132)
constexpr int SM_Y    = 49920;             // 768
constexpr int SM_S12  = 50688;             // 768
constexpr int SM_TOT  = 51456;             // 205824 bytes

DEVINL float sanf(float x) {
    if (isnan(x)) return 0.0f;
    if (isinf(x)) return 9999.0f;
    return x;
}

DEVINL float fast_tanh(float x) {
    float ax = fabsf(x) * 2.8853900817779268f;  // 2*log2(e)
    float e; asm("ex2.approx.f32 %0, %1;" : "=f"(e) : "f"(ax));
    float r; asm("rcp.approx.f32 %0, %1;" : "=f"(r) : "f"(e + 1.0f));
    float t = fmaf(-2.0f, r, 1.0f);
    return copysignf(t, x);
}

DEVINL float tf32f(float x) {
    u32 y; asm("cvt.rna.tf32.f32 %0, %1;" : "=r"(y) : "f"(x));
    return __uint_as_float(y);
}

DEVINL void mma8(float* d, const u32* a, u32 b0, u32 b1) {
    asm("mma.sync.aligned.m16n8k8.row.col.f32.tf32.tf32.f32 "
        "{%0,%1,%2,%3}, {%4,%5,%6,%7}, {%8,%9}, {%0,%1,%2,%3};"
        : "+f"(d[0]), "+f"(d[1]), "+f"(d[2]), "+f"(d[3])
        : "r"(a[0]), "r"(a[1]), "r"(a[2]), "r"(a[3]), "r"(b0), "r"(b1));
}

DEVINL void cpa16(void* dst, const void* src) {
    unsigned sa = (unsigned)__cvta_generic_to_shared(dst);
    asm volatile("cp.async.cg.shared.global [%0], [%1], 16;" :: "r"(sa), "l"(src));
}
DEVINL void cpa_commit() { asm volatile("cp.async.commit_group;"); }
DEVINL void cpa_wait0()  { asm volatile("cp.async.wait_group 0;"); }

// ---------- prepack: W[K][N] -> fragment pairs (tf32-rounded) ----------
// pair p of a segment: ks, nt, lane; b0 = W[8ks + (lane&3)][8nt + (lane>>2)], b1 = +4 k.
__global__ void prepack_kernel(const float* __restrict__ Wc2,
                               const float* __restrict__ Wp2,
                               const float* __restrict__ Wl1)
{
    int idx = blockIdx.x * blockDim.x + threadIdx.x;
    if (idx >= NPAIR) return;
    const float* W; int p, N, ks, nt, lane;
    if (idx < OP2)      { W = Wc2; p = idx;       N = 256; ks = p >> 10; int rem = p & 1023; nt = rem >> 5; lane = rem & 31; }
    else if (idx < OL1) { W = Wp2; p = idx - OP2; N = 256; ks = p >> 10; int rem = p & 1023; nt = rem >> 5; lane = rem & 31; }
    else                { W = Wl1; p = idx - OL1; N = 128; ks = p >> 9;  int rem = p & 511;  nt = rem >> 5; lane = rem & 31; }
    int k0 = 8 * ks + (lane & 3);
    int n  = 8 * nt + (lane >> 2);
    float2 v;
    v.x = tf32f(W[k0 * N + n]);
    v.y = tf32f(W[(k0 + 4) * N + n]);
    g_packed[idx] = v;
}

// ---------- layer1: A[M][KA] @ W[KA][128] + b -> prelu -> U (stride STRU, tf32) ----------
template<int M, int KA>
DEVINL void layer1(const float* __restrict__ A, const float* __restrict__ WT,
                   const float* __restrict__ bg, float alpha,
                   float* __restrict__ U, int tx, int ty)
{
    constexpr int RPT = M / 16;
    float acc[RPT][4];
#pragma unroll
    for (int r = 0; r < RPT; r++)
#pragma unroll
        for (int j = 0; j < 4; j++) acc[r][j] = 0.0f;

#pragma unroll
    for (int k = 0; k < KA; k += 4) {
        float a[RPT][4];
#pragma unroll
        for (int r = 0; r < RPT; r++) {
            float4 v = *(const float4*)&A[(ty * RPT + r) * KA + k];
            a[r][0] = v.x; a[r][1] = v.y; a[r][2] = v.z; a[r][3] = v.w;
        }
#pragma unroll
        for (int j4 = 0; j4 < 4; j4++) {
            float w[4];
#pragma unroll
            for (int j = 0; j < 4; j++) w[j] = WT[(k + j4) * 128 + tx + 32 * j];
#pragma unroll
            for (int r = 0; r < RPT; r++)
#pragma unroll
                for (int j = 0; j < 4; j++)
                    acc[r][j] = fmaf(a[r][j4], w[j], acc[r][j]);
        }
    }
#pragma unroll
    for (int r = 0; r < RPT; r++)
#pragma unroll
        for (int j = 0; j < 4; j++) {
            int c = tx + 32 * j;
            float v = acc[r][j] + bg[c];
            v = (v >= 0.0f) ? v : alpha * v;
            U[(ty * RPT + r) * STRU + c] = tf32f(v);
        }
}

// ---------- layer2 (mma): U[M][128] @ W[128][256] + b -> tanh -> CHPA[:, colOff..) ----------
template<int M>
DEVINL void layer2(const float* __restrict__ U, const float2* __restrict__ Pg,
                   const float* __restrict__ bg, float* __restrict__ CH, int colOff,
                   float* __restrict__ WTf, int tid)
{
    constexpr int MP = M / 32, NPW = 16 / MP, NT = 32 / NPW;
    const int w = tid >> 5, lane = tid & 31;
    const int mi = w % MP, ni = w / MP;
    const int mr = mi * 32, nb8 = ni * NT;
    const int r = lane >> 2, cth = lane & 3;
    const u32* Uu = (const u32*)U;

    float bias[NT][2];
#pragma unroll
    for (int nt = 0; nt < NT; nt++) {
        int c0 = (nb8 + nt) * 8 + 2 * cth;
        bias[nt][0] = bg[c0]; bias[nt][1] = bg[c0 + 1];
    }
    float acc[2][NT][4];
#pragma unroll
    for (int mt = 0; mt < 2; mt++)
#pragma unroll
        for (int nt = 0; nt < NT; nt++)
#pragma unroll
            for (int j = 0; j < 4; j++) acc[mt][nt][j] = 0.0f;

    // preload tile 0 (2 ksteps = 2048 pairs = 16KB)
    for (int s = tid; s < 1024; s += NTH) cpa16((float2*)WTf + s * 2, Pg + s * 2);
    cpa_commit(); cpa_wait0();
    __syncthreads();

    for (int t = 0; t < 8; t++) {
        const u64* bt = (const u64*)((const float2*)WTf + (t & 1) * 2048);
        if (t + 1 < 8) {
            float2* nbuf = (float2*)WTf + ((t + 1) & 1) * 2048;
            const float2* ns = Pg + (t + 1) * 2048;
            for (int s = tid; s < 1024; s += NTH) cpa16(nbuf + s * 2, ns + s * 2);
            cpa_commit();
        }
#pragma unroll
        for (int kk = 0; kk < 2; kk++) {
            const int kA = (2 * t + kk) * 8;
            u32 a[2][4];
#pragma unroll
            for (int mt = 0; mt < 2; mt++) {
                int base = (mr + mt * 16 + r) * STRU + kA + cth;
                a[mt][0] = Uu[base];
                a[mt][1] = Uu[base + 8 * STRU];
                a[mt][2] = Uu[base + 4];
                a[mt][3] = Uu[base + 8 * STRU + 4];
            }
#pragma unroll
            for (int nt = 0; nt < NT; nt++) {
                u64 b = bt[(kk * 32 + nb8 + nt) * 32 + lane];
                u32 b0 = (u32)b, b1 = (u32)(b >> 32);
#pragma unroll
                for (int mt = 0; mt < 2; mt++) mma8(acc[mt][nt], a[mt], b0, b1);
            }
        }
        cpa_wait0();
        __syncthreads();
    }
#pragma unroll
    for (int mt = 0; mt < 2; mt++)
#pragma unroll
        for (int nt = 0; nt < NT; nt++) {
            int row0 = mr + mt * 16 + r;
            int c0 = colOff + (nb8 + nt) * 8 + 2 * cth;
            float2 v0, v1;
            v0.x = tf32f(fast_tanh(acc[mt][nt][0] + bias[nt][0]));
            v0.y = tf32f(fast_tanh(acc[mt][nt][1] + bias[nt][1]));
            v1.x = tf32f(fast_tanh(acc[mt][nt][2] + bias[nt][0]));
            v1.y = tf32f(fast_tanh(acc[mt][nt][3] + bias[nt][1]));
            *(float2*)&CH[row0 * STRC + c0] = v0;
            *(float2*)&CH[(row0 + 8) * STRC + c0] = v1;
        }
}

// ---------- layer3 (mma, split-K 2): CHPA[M][512] @ Wl1[512][128] + b -> tanh -> H ----------
template<int M>
DEVINL void layer3(const float* __restrict__ CP, const float2* __restrict__ Pg,
                   const float* __restrict__ bl1, float* __restrict__ H,
                   float* __restrict__ WTf, int tid)
{
    constexpr int MP = M / 32, NPW = 8 / MP, NT = 16 / NPW;
    const int w = tid >> 5, lane = tid & 31;
    const int kg = w >> 3, wl = w & 7;
    const int mi = wl % MP, ni = wl / MP;
    const int mr = mi * 32, nb8 = ni * NT;
    const int r = lane >> 2, cth = lane & 3;
    const u32* Cu = (const u32*)CP;

    float acc[2][NT][4];
#pragma unroll
    for (int mt = 0; mt < 2; mt++)
#pragma unroll
        for (int nt = 0; nt < NT; nt++)
#pragma unroll
            for (int j = 0; j < 4; j++) acc[mt][nt][j] = 0.0f;

    // tile t: kg0 ks{2t,2t+1} at pairs [0,1024), kg1 ks{32+2t,...} at [1024,2048)
    {
        for (int s = tid; s < 1024; s += NTH) {
            int half = s >> 9, off = s & 511;
            const float2* src = Pg + (half ? (32) : 0) * 512 + off * 2;
            cpa16((float2*)WTf + s * 2, src);
        }
        cpa_commit(); cpa_wait0();
        __syncthreads();
    }
    for (int t = 0; t < 16; t++) {
        const u64* bt = (const u64*)((const float2*)WTf + (t & 1) * 2048);
        if (t + 1 < 16) {
            float2* nbuf = (float2*)WTf + ((t + 1) & 1) * 2048;
            for (int s = tid; s < 1024; s += NTH) {
                int half = s >> 9, off = s & 511;
                const float2* src = Pg + (half ? (32 + 2 * (t + 1)) : (2 * (t + 1))) * 512 + off * 2;
                cpa16(nbuf + s * 2, src);
            }
            cpa_commit();
        }
#pragma unroll
        for (int kk = 0; kk < 2; kk++) {
            const int kA = (kg * 32 + 2 * t + kk) * 8;
            u32 a[2][4];
#pragma unroll
            for (int mt = 0; mt < 2; mt++) {
                int base = (mr + mt * 16 + r) * STRC + kA + cth;
                a[mt][0] = Cu[base];
                a[mt][1] = Cu[base + 8 * STRC];
                a[mt][2] = Cu[base + 4];
                a[mt][3] = Cu[base + 8 * STRC + 4];
            }
#pragma unroll
            for (int nt = 0; nt < NT; nt++) {
                u64 b = bt[((kg * 2 + kk) * 16 + nb8 + nt) * 32 + lane];
                u32 b0 = (u32)b, b1 = (u32)(b >> 32);
#pragma unroll
                for (int mt = 0; mt < 2; mt++) mma8(acc[mt][nt], a[mt], b0, b1);
            }
        }
        cpa_wait0();
        __syncthreads();
    }
    // reduce split-K partials via PART (aliases WT, stride STRU)
    float* PART = WTf;
    if (kg == 1) {
#pragma unroll
        for (int mt = 0; mt < 2; mt++)
#pragma unroll
            for (int nt = 0; nt < NT; nt++) {
                int row0 = mr + mt * 16 + r;
                int c0 = (nb8 + nt) * 8 + 2 * cth;
                float2 v0 = { acc[mt][nt][0], acc[mt][nt][1] };
                float2 v1 = { acc[mt][nt][2], acc[mt][nt][3] };
                *(float2*)&PART[row0 * STRU + c0] = v0;
                *(float2*)&PART[(row0 + 8) * STRU + c0] = v1;
            }
    }
    __syncthreads();
    if (kg == 0) {
#pragma unroll
        for (int mt = 0; mt < 2; mt++)
#pragma unroll
            for (int nt = 0; nt < NT; nt++) {
                int row0 = mr + mt * 16 + r;
                int c0 = (nb8 + nt) * 8 + 2 * cth;
                float2 p0 = *(const float2*)&PART[row0 * STRU + c0];
                float2 p1 = *(const float2*)&PART[(row0 + 8) * STRU + c0];
                float b0 = bl1[c0], b1 = bl1[c0 + 1];
                H[row0 * STRU + c0]           = fast_tanh(acc[mt][nt][0] + p0.x + b0);
                H[row0 * STRU + c0 + 1]       = fast_tanh(acc[mt][nt][1] + p0.y + b1);
                H[(row0 + 8) * STRU + c0]     = fast_tanh(acc[mt][nt][2] + p1.x + b0);
                H[(row0 + 8) * STRU + c0 + 1] = fast_tanh(acc[mt][nt][3] + p1.y + b1);
            }
    }
}

// ---------- layer4: H[M][128] @ Wl2[128][32] + b -> prelu -> S12 / out ----------
template<int M, bool FINAL>
DEVINL void layer4(const float* __restrict__ H, const float* __restrict__ WT,
                   const float* __restrict__ bl2, float al,
                   float* __restrict__ S12, float* __restrict__ out,
                   int b0, int nb, int tx, int ty)
{
    constexpr int RPT = M / 16;
    float acc[RPT];
#pragma unroll
    for (int r = 0; r < RPT; r++) acc[r] = 0.0f;
#pragma unroll
    for (int k = 0; k < 128; k += 4) {
        float a[RPT][4];
#pragma unroll
        for (int r = 0; r < RPT; r++) {
            float4 v = *(const float4*)&H[(ty * RPT + r) * STRU + k];
            a[r][0] = v.x; a[r][1] = v.y; a[r][2] = v.z; a[r][3] = v.w;
        }
#pragma unroll
        for (int j = 0; j < 4; j++) {
            float wv = WT[(k + j) * 32 + tx];
#pragma unroll
            for (int r = 0; r < RPT; r++) acc[r] = fmaf(a[r][j], wv, acc[r]);
        }
    }
#pragma unroll
    for (int r = 0; r < RPT; r++) {
        float v = acc[r] + bl2[tx];
        v = (v >= 0.0f) ? v : al * v;
        int row = ty * RPT + r;
        if (FINAL) {
            int be = b0 + (row >> 1);
            if (be < nb) out[(size_t)be * 64 + (row & 1) * 32 + tx] = v;
        } else {
            if (tx < 12) S12[row * 12 + tx] = v;
        }
    }
}

// ---------- full combine() pipeline for M rows ----------
template<int M, bool FINAL>
DEVINL void pipeline(float* sm, int tid,
                     const float* Wc1, const float* bc1, float ac,
                     const float* bc2,
                     const float* Wp1, const float* bp1, float ap,
                     const float* bp2,
                     const float* bl1,
                     const float* Wl2, const float* bl2, float al,
                     float* out, int b0, int nb)
{
    float* U    = sm + SM_U;      // also H (alias)
    float* CHPA = sm + SM_CHPA;
    float* WT   = sm + SM_WT;
    float* X    = sm + SM_CHPA;   // alias (consumed before CHPA written)
    float* Y    = sm + SM_Y;
    float* S12  = sm + SM_S12;
    const int tx = tid & 31, ty = tid >> 5;
    const float2* gP = g_packed;

    // A1: U = prelu(X @ Wc1 + bc1)
    for (int i = tid; i < 24 * 128; i += NTH) WT[i] = Wc1[i];
    __syncthreads();
    layer1<M, 24>(X, WT, bc1, ac, U, tx, ty);
    __syncthreads();
    // B1: ch -> CHPA cols [0,256)
    layer2<M>(U, gP + OC2, bc2, CHPA, 0, WT, tid);
    __syncthreads();
    // A2: V = prelu(Y @ Wp1 + bp1) (overwrites U)
    for (int i = tid; i < 12 * 128; i += NTH) WT[i] = Wp1[i];
    __syncthreads();
    layer1<M, 12>(Y, WT, bp1, ap, U, tx, ty);
    __syncthreads();
    // B2: pa -> CHPA cols [256,512)
    layer2<M>(U, gP + OP2, bp2, CHPA, 256, WT, tid);
    __syncthreads();
    // C: h = tanh(CHPA @ Wl1 + bl1) -> H (aliases U)
    layer3<M>(CHPA, gP + OL1, bl1, U, WT, tid);
    __syncthreads();
    // D: out = prelu(h @ Wl2 + bl2)
    for (int i = tid; i < 128 * 32; i += NTH) WT[i] = Wl2[i];
    __syncthreads();
    layer4<M, FINAL>(U, WT, bl2, al, S12, out, b0, nb, tx, ty);
}

__global__ void __launch_bounds__(NTH, 1)
rvnn_kernel(const float* __restrict__ level1, const float* __restrict__ level2,
            const float* __restrict__ level3,
            const float* __restrict__ Wc1, const float* __restrict__ bc1, const float* __restrict__ ac,
            const float* __restrict__ bc2,
            const float* __restrict__ Wp1, const float* __restrict__ bp1, const float* __restrict__ ap,
            const float* __restrict__ bp2,
            const float* __restrict__ bl1,
            const float* __restrict__ Wl2, const float* __restrict__ bl2, const float* __restrict__ al,
            float* __restrict__ out, int nb)
{
    extern __shared__ float sm[];
    const int tid = threadIdx.x;
    const int b0 = blockIdx.x * BB;
    const float acv = *ac, apv = *ap, alv = *al;

    float* X   = sm + SM_CHPA;
    float* Y   = sm + SM_Y;
    float* S12 = sm + SM_S12;

    // ---- stage 1 input staging ----
    {
        const float* src = level3 + (size_t)b0 * 96;
        int lim = (nb - b0 < BB ? nb - b0 : BB) * 96;
        for (int i = tid; i < BB * 96; i += NTH) {
            float v = (i < lim) ? sanf(src[i]) : 0.0f;
            int be = i / 96, rem = i % 96, c = rem / 12, k = rem % 12;
            int p = c >> 1, s = c & 1;
            X[(be * 4 + p) * 24 + (1 - s) * 12 + k] = v;
        }
    }
    {
        const float* src = level2 + (size_t)b0 * 48;
        int lim = (nb - b0 < BB ? nb - b0 : BB) * 48;
        for (int i = tid; i < BB * 48; i += NTH) {
            float v = (i < lim) ? sanf(src[i]) : 0.0f;
            int be = i / 48, rem = i % 48, p = rem / 12, k = rem % 12;
            Y[(be * 4 + p) * 12 + k] = v;
        }
    }
    __syncthreads();

    pipeline<64, false>(sm, tid, Wc1, bc1, acv, bc2, Wp1, bp1, apv,
                        bp2, bl1, Wl2, bl2, alv, out, b0, nb);
    __syncthreads();

    // ---- stage 2 input staging ----
    for (int i = tid; i < 32 * 24; i += NTH) {
        int r2 = i / 24, k24 = i % 24, be = r2 >> 1, p = r2 & 1;
        int j = 2 * p + (k24 < 12 ? 1 : 0);
        int k = (k24 < 12) ? k24 : (k24 - 12);
        X[r2 * 24 + k24] = sanf(S12[(be * 4 + j) * 12 + k]);
    }
    {
        const float* src = level1 + (size_t)b0 * 24;
        int lim = (nb - b0 < BB ? nb - b0 : BB) * 24;
        for (int i = tid; i < BB * 24; i += NTH) {
            float v = (i < lim) ? sanf(src[i]) : 0.0f;
            int be = i / 24, rem = i % 24, p = rem / 12, k = rem % 12;
            Y[(be * 2 + p) * 12 + k] = v;
        }
    }
    __syncthreads();

    pipeline<32, true>(sm, tid, Wc1, bc1, acv, bc2, Wp1, bp1, apv,
                       bp2, bl1, Wl2, bl2, alv, out, b0, nb);
}

extern "C" void kernel_launch(void* const* d_in, const int* in_sizes, int n_in,
                              void* d_out, int out_size) {
    const float* level1 = (const float*)d_in[0];
    const float* level2 = (const float*)d_in[1];
    const float* level3 = (const float*)d_in[2];
    const float* Wc1 = (const float*)d_in[3];
    const float* bc1 = (const float*)d_in[4];
    const float* ac  = (const float*)d_in[5];
    const float* Wc2 = (const float*)d_in[6];
    const float* bc2 = (const float*)d_in[7];
    const float* Wp1 = (const float*)d_in[8];
    const float* bp1 = (const float*)d_in[9];
    const float* ap  = (const float*)d_in[10];
    const float* Wp2 = (const float*)d_in[11];
    const float* bp2 = (const float*)d_in[12];
    const float* Wl1 = (const float*)d_in[13];
    const float* bl1 = (const float*)d_in[14];
    const float* Wl2 = (const float*)d_in[15];
    const float* bl2 = (const float*)d_in[16];
    const float* al  = (const float*)d_in[17];
    float* out = (float*)d_out;

    int nb = in_sizes[0] / 24;
    int grid = (nb + BB - 1) / BB;
    size_t smem = (size_t)SM_TOT * sizeof(float);  // 205824 B

    prepack_kernel<<<(NPAIR + 255) / 256, 256>>>(Wc2, Wp2, Wl1);

    cudaFuncSetAttribute(rvnn_kernel, cudaFuncAttributeMaxDynamicSharedMemorySize, (int)smem);
    rvnn_kernel<<<grid, NTH, smem>>>(level1, level2, level3, Wc1, bc1, ac, bc2,
                                     Wp1, bp1, ap, bp2, bl1, Wl2, bl2, al,
                                     out, nb);
}